// round 13
// baseline (speedup 1.0000x reference)
#include <cuda_runtime.h>
#include <cuda_fp16.h>

// ---------------------------------------------------------------------------
// KPlaneRBFField on GB300 — round 13.
//  Merged field kernel, 4 pts/warp, 8 lanes/pt. Every plane sample = 2
//  LDG.128 covering the full 128B (x0|x1) texel-pair line (2 lines/pt/sample,
//  halved vs R10). x-combine via weighted partials + 2 SHFL (no select storm
//  that killed R11). lc0 read as contiguous 128B i2-pairs. One 128B output
//  row store per point per segment. prep/scan/scatter as R10/R12.
// ---------------------------------------------------------------------------

#define NSIDE 64
#define MAXN  524288
#define NBUCK 32768
#define TP_POS 128

__device__ __half   g_planesTh[33030144];  // 66 MB transposed fp16 planes
__device__ __half   g_lc0h[8388608];       // 16.5 MB fp16 codes
__device__ unsigned g_hist[NBUCK];
__device__ unsigned g_blksum[32];
__device__ unsigned g_key[MAXN];
__device__ float4   g_spts[MAXN];          // sorted (xs0,xs1,xs2,pid)

__constant__ int c_plane_off[9] = {
    0,        524288,   1048576,
    1572864,  3670016,  5767168,
    7864320,  16252928, 24641536
};
__constant__ int c_blkCum[10] = {0,128,256,384,896,1408,1920,3968,6016,8064};
__constant__ int c_res[9]     = {128,128,128,256,256,256,512,512,512};

struct PrepArgs {
    const float* p[9];
    const float* lc0;
    const float* pts;
    const float* aabb;
    int n;
};

__device__ __forceinline__ unsigned spread3(unsigned x)
{
    x &= 0x3FF;
    x = (x | (x << 16)) & 0x30000FF;
    x = (x | (x << 8))  & 0x300F00F;
    x = (x | (x << 4))  & 0x30C30C3;
    x = (x | (x << 2))  & 0x9249249;
    return x;
}

// ---------------- k1: transpose + lc0 convert + histogram -------------------
__global__ void __launch_bounds__(256) prep_kernel(PrepArgs a)
{
    int b = blockIdx.x;
    int tid = threadIdx.x;

    if (b >= 16256) {                       // Morton histogram
        int i = (b - 16256) * 256 + tid;
        if (i >= a.n) return;
        float a0x = a.aabb[0], a0y = a.aabb[1], a0z = a.aabb[2];
        float a1x = a.aabb[3], a1y = a.aabb[4], a1z = a.aabb[5];
        float x = (a.pts[3 * i + 0] - a0x) * (2.0f / (a1x - a0x)) - 1.0f;
        float y = (a.pts[3 * i + 1] - a0y) * (2.0f / (a1y - a0y)) - 1.0f;
        float z = (a.pts[3 * i + 2] - a0z) * (2.0f / (a1z - a0z)) - 1.0f;
        int qx = min(max((int)((x + 1.0f) * 16.0f), 0), 31);
        int qy = min(max((int)((y + 1.0f) * 16.0f), 0), 31);
        int qz = min(max((int)((z + 1.0f) * 16.0f), 0), 31);
        unsigned key = (spread3(qx) << 2) | (spread3(qy) << 1) | spread3(qz);
        g_key[i] = key;
        atomicAdd(&g_hist[key], 1u);
        return;
    }
    if (b >= 8064) {                        // lc0 convert
        int i = (b - 8064) * 256 + tid;
        float4 v = __ldg((const float4*)a.lc0 + i);
        __half2 h0 = __floats2half2_rn(v.x, v.y);
        __half2 h1 = __floats2half2_rn(v.z, v.w);
        ((uint2*)g_lc0h)[i] = make_uint2(*(unsigned*)&h0, *(unsigned*)&h1);
        return;
    }

    // plane transpose
    __shared__ float tile[TP_POS][33];
    int pi = 0;
    #pragma unroll
    for (int i = 1; i < 9; i++) pi += (b >= c_blkCum[i]) ? 1 : 0;
    int r  = c_res[pi];
    int rr = r * r;
    int posBase = (b - c_blkCum[pi]) * TP_POS;
    const float4* src4 = (const float4*)a.p[pi];
    int rr4 = rr >> 2;
    int pb4 = posBase >> 2;

    #pragma unroll
    for (int it = 0; it < 4; it++) {
        int v  = tid + it * 256;
        int ch = v >> 5;
        int pv = v & 31;
        float4 val = src4[ch * rr4 + pb4 + pv];
        int p = pv << 2;
        tile[p + 0][ch] = val.x;
        tile[p + 1][ch] = val.y;
        tile[p + 2][ch] = val.z;
        tile[p + 3][ch] = val.w;
    }
    __syncthreads();

    uint2* dst2 = (uint2*)(g_planesTh + c_plane_off[pi]) + posBase * 8;
    #pragma unroll
    for (int it = 0; it < 4; it++) {
        int v  = tid + it * 256;
        int p  = v >> 3;
        int c4 = (v & 7) << 2;
        __half2 h0 = __floats2half2_rn(tile[p][c4 + 0], tile[p][c4 + 1]);
        __half2 h1 = __floats2half2_rn(tile[p][c4 + 2], tile[p][c4 + 3]);
        dst2[v] = make_uint2(*(unsigned*)&h0, *(unsigned*)&h1);
    }
}

// ---------------- k2: scan ---------------------------------------------------
__global__ void __launch_bounds__(1024) scan1_kernel()
{
    __shared__ unsigned wsum[32];
    int t = threadIdx.x;
    int lane = t & 31;
    int wid = t >> 5;
    int i = blockIdx.x * 1024 + t;
    unsigned v = g_hist[i];

    unsigned x = v;
    #pragma unroll
    for (int off = 1; off < 32; off <<= 1) {
        unsigned y = __shfl_up_sync(0xFFFFFFFFu, x, off);
        if (lane >= off) x += y;
    }
    if (lane == 31) wsum[wid] = x;
    __syncthreads();
    if (wid == 0) {
        unsigned w = wsum[lane];
        unsigned ww = w;
        #pragma unroll
        for (int off = 1; off < 32; off <<= 1) {
            unsigned y = __shfl_up_sync(0xFFFFFFFFu, ww, off);
            if (lane >= off) ww += y;
        }
        wsum[lane] = ww - w;
        if (lane == 31) g_blksum[blockIdx.x] = ww;
    }
    __syncthreads();
    g_hist[i] = x + wsum[wid] - v;
}

// ---------------- k3: scatter -------------------------------------------------
__global__ void scatter_kernel(const float* __restrict__ pts,
                               const float* __restrict__ aabb, int n)
{
    __shared__ unsigned blkoff[32];
    int t = threadIdx.x;
    if (t < 32) {
        unsigned v = g_blksum[t];
        unsigned x = v;
        #pragma unroll
        for (int off = 1; off < 32; off <<= 1) {
            unsigned y = __shfl_up_sync(0xFFFFFFFFu, x, off);
            if (t >= off) x += y;
        }
        blkoff[t] = x - v;
    }
    __syncthreads();

    int i = blockIdx.x * blockDim.x + t;
    if (i >= n) return;
    unsigned key = g_key[i];
    unsigned pos = atomicAdd(&g_hist[key], 1u) + blkoff[key >> 10];

    float a0x = aabb[0], a0y = aabb[1], a0z = aabb[2];
    float a1x = aabb[3], a1y = aabb[4], a1z = aabb[5];
    float xs0 = (pts[3 * i + 0] - a0x) * (2.0f / (a1x - a0x)) - 1.0f;
    float xs1 = (pts[3 * i + 1] - a0y) * (2.0f / (a1y - a0y)) - 1.0f;
    float xs2 = (pts[3 * i + 2] - a0z) * (2.0f / (a1z - a0z)) - 1.0f;
    g_spts[pos] = make_float4(xs0, xs1, xs2, __int_as_float(i));
}

__global__ void ident_kernel(const float* __restrict__ pts,
                             const float* __restrict__ aabb, int n)
{
    int i = blockIdx.x * blockDim.x + threadIdx.x;
    if (i >= n) return;
    float a0x = aabb[0], a0y = aabb[1], a0z = aabb[2];
    float a1x = aabb[3], a1y = aabb[4], a1z = aabb[5];
    float xs0 = (pts[3 * i + 0] - a0x) * (2.0f / (a1x - a0x)) - 1.0f;
    float xs1 = (pts[3 * i + 1] - a0y) * (2.0f / (a1y - a0y)) - 1.0f;
    float xs2 = (pts[3 * i + 2] - a0z) * (2.0f / (a1z - a0z)) - 1.0f;
    g_spts[i] = make_float4(xs0, xs1, xs2, __int_as_float(i));
}

// ---------------- fp16 helpers ------------------------------------------------
__device__ __forceinline__ __half2 u2h2(unsigned u)
{
    __half2 h;
    *(unsigned*)&h = u;
    return h;
}

// One bilinear sample; lane returns float4 for chans (8m + 4s .. +4).
// Warp: 2 LDG.128 (4 pts x 1 line each), y-lerp half2 local, x-combine via
// weighted partials + 2 SHFL.
__device__ __forceinline__ float4 sampleX(const __half* __restrict__ T, int r,
                                          float u, float v, int k, int s)
{
    float fr = (float)(r - 1);
    float fx = (u + 1.0f) * 0.5f * fr;
    float fy = (v + 1.0f) * 0.5f * fr;
    float flx = fminf(fmaxf(floorf(fx), 0.0f), (float)(r - 2));
    float fly = fminf(fmaxf(floorf(fy), 0.0f), (float)(r - 2));
    float wx = fx - flx;
    float wy = fy - fly;
    int ix = (int)flx;
    int iy = (int)fly;

    // 128B line = texel(ix):32ch | texel(ix+1):32ch. Lane k takes 16B.
    const uint4* b = (const uint4*)(T + ((iy * r + ix) << 5)) + k;
    uint4 R0 = __ldg(b);              // row y0
    uint4 R1 = __ldg(b + (r << 2));   // row y1 (r*64B = r*4 uint4)

    // y-lerp (local, half2)
    __half2 wy2 = __float2half2_rn(wy);
    const __half2* a0 = (const __half2*)&R0;
    const __half2* a1 = (const __half2*)&R1;
    unsigned pu[4];
    // x-side weight: s=1 -> wx ; s=0 -> 1-wx, complement formed in half so
    // the two sides sum to ~1.
    __half hx = __float2half_rn(wx);
    __half hw = s ? hx : __hsub(__float2half_rn(1.0f), hx);
    __half2 w2 = __half2half2(hw);
    #pragma unroll
    for (int j = 0; j < 4; j++) {
        __half2 vv = __hfma2(__hsub2(a1[j], a0[j]), wy2, a0[j]);
        __half2 pj = __hmul2(vv, w2);                  // weighted partial
        pu[j] = *(unsigned*)&pj;
    }

    // own regs = chans halves [2s,2s+1]; send the other pair (partner's own)
    unsigned own0 = s ? pu[2] : pu[0];
    unsigned own1 = s ? pu[3] : pu[1];
    unsigned snd0 = s ? pu[0] : pu[2];
    unsigned snd1 = s ? pu[1] : pu[3];
    unsigned rcv0 = __shfl_xor_sync(0xFFFFFFFFu, snd0, 4);
    unsigned rcv1 = __shfl_xor_sync(0xFFFFFFFFu, snd1, 4);
    __half2 c0 = __hadd2(u2h2(own0), u2h2(rcv0));
    __half2 c1 = __hadd2(u2h2(own1), u2h2(rcv1));
    float2 f0 = __half22float2(c0);
    float2 f1 = __half22float2(c1);
    return make_float4(f0.x, f0.y, f1.x, f1.y);
}

// ---------------- k4: field kernel: 4 pts/warp, 8 lanes/pt -------------------
__global__ void __launch_bounds__(256, 4) field_kernel(
    const float* __restrict__ ks,
    const float* __restrict__ kpb,
    float* __restrict__ out,
    int npts)
{
    int gwarp = (int)((blockIdx.x * blockDim.x + threadIdx.x) >> 5);
    int lane  = threadIdx.x & 31;
    int p = lane >> 3;                 // point in warp
    int k = lane & 7;                  // lane within point
    int s = k >> 2;                    // side
    int m = k & 3;                     // 16B chunk -> chans 8m..8m+7

    int slot = gwarp * 4 + p;
    bool valid = slot < npts;
    int cslot = valid ? slot : (npts - 1);

    float4 sp = __ldg(&g_spts[cslot]);
    float xs0 = sp.x, xs1 = sp.y, xs2 = sp.z;
    int pid = __float_as_int(sp.w);

    float* outP = out + (size_t)pid * 128;
    const float4* kpb4 = (const float4*)kpb;
    int co = (m << 3) + (s << 2);      // this lane's stored chan offset

    const int resArr[3] = {128, 256, 512};
    #pragma unroll
    for (int g = 0; g < 3; g++) {
        int r = resArr[g];
        float4 f0 = sampleX(g_planesTh + c_plane_off[g * 3 + 0], r, xs0, xs1, k, s);
        float4 f1 = sampleX(g_planesTh + c_plane_off[g * 3 + 1], r, xs0, xs2, k, s);
        float4 f2 = sampleX(g_planesTh + c_plane_off[g * 3 + 2], r, xs1, xs2, k, s);
        float4 bias = __ldg(kpb4 + g * 8 + 2 * m + s);
        float4 o;
        o.x = f0.x * f1.x * f2.x + bias.x;
        o.y = f0.y * f1.y * f2.y + bias.y;
        o.z = f0.z * f1.z * f2.z + bias.z;
        o.w = f0.w * f1.w * f2.w + bias.w;
        if (valid)
            __stcs((float4*)(outP + g * 32 + co), o);  // 128B row per point
    }

    // ---- RBF: 8 corners as 4 contiguous i2-pairs; lane side s = corner ci2+s
    const float interval = 2.0f / (float)(NSIDE - 1);
    float c0f = fminf(fmaxf(floorf((xs0 + 1.0f) / interval), 0.0f), (float)(NSIDE - 2));
    float c1f = fminf(fmaxf(floorf((xs1 + 1.0f) / interval), 0.0f), (float)(NSIDE - 2));
    float c2f = fminf(fmaxf(floorf((xs2 + 1.0f) / interval), 0.0f), (float)(NSIDE - 2));
    int ci0 = (int)c0f, ci1 = (int)c1f, ci2 = (int)c2f;

    float d2c = xs2 - (-1.0f + (float)(ci2 + s) * interval);
    float d2c2 = d2c * d2c;

    float acc[8] = {0.f, 0.f, 0.f, 0.f, 0.f, 0.f, 0.f, 0.f};
    float wsumOwn = 0.0f;
    #pragma unroll
    for (int mp = 0; mp < 4; mp++) {
        int i0 = ci0 + (mp >> 1);
        int i1 = ci1 + (mp & 1);
        int idx0 = (i0 * NSIDE + i1) * NSIDE + ci2;     // pair base
        float sv = __ldg(&ks[idx0 + s]);
        float d0 = xs0 - (-1.0f + (float)i0 * interval);
        float d1 = xs1 - (-1.0f + (float)i1 * interval);
        float dist2 = d0 * d0 + d1 * d1 + d2c2;
        float phi = 1.0f / (1.0f + dist2 * sv * sv);
        wsumOwn += phi;
        // 128B pair line: corner(ci2):32ch | corner(ci2+1):32ch ; lane takes 16B
        uint4 cu = __ldg((const uint4*)(g_lc0h + (idx0 << 5)) + k);
        float2 ca = __half22float2(u2h2(cu.x));
        float2 cb = __half22float2(u2h2(cu.y));
        float2 cc = __half22float2(u2h2(cu.z));
        float2 cd = __half22float2(u2h2(cu.w));
        acc[0] += phi * ca.x;  acc[1] += phi * ca.y;
        acc[2] += phi * cb.x;  acc[3] += phi * cb.y;
        acc[4] += phi * cc.x;  acc[5] += phi * cc.y;
        acc[6] += phi * cd.x;  acc[7] += phi * cd.y;
    }
    float wsum = wsumOwn + __shfl_xor_sync(0xFFFFFFFFu, wsumOwn, 4);

    // exchange: send partner's stored quad, receive ours; add.
    float fin[4];
    #pragma unroll
    for (int j = 0; j < 4; j++) {
        float ownv = s ? acc[4 + j] : acc[j];
        float sndv = s ? acc[j]     : acc[4 + j];
        float rcvv = __shfl_xor_sync(0xFFFFFFFFu, sndv, 4);
        fin[j] = ownv + rcvv;
    }

    float inv = 1.0f / (wsum + 1e-8f);
    float4 bias = __ldg(kpb4 + 24 + 2 * m + s);
    float4 o;
    o.x = fin[0] * inv + bias.x;
    o.y = fin[1] * inv + bias.y;
    o.z = fin[2] * inv + bias.z;
    o.w = fin[3] * inv + bias.w;
    if (valid)
        __stcs((float4*)(outP + 96 + co), o);
}

// ------------------------------ launcher ------------------------------------
extern "C" void kernel_launch(void* const* d_in, const int* in_sizes, int n_in,
                              void* d_out, int out_size)
{
    const float* pts  = (const float*)d_in[0];
    const float* aabb = (const float*)d_in[1];
    const float* lc0  = (const float*)d_in[11];
    const float* ks   = (const float*)d_in[12];
    const float* kpb  = (const float*)d_in[13];
    float* out = (float*)d_out;

    int npts = in_sizes[0] / 3;

    void* histPtr = nullptr;
    cudaGetSymbolAddress(&histPtr, g_hist);
    cudaMemsetAsync(histPtr, 0, NBUCK * sizeof(unsigned));

    PrepArgs a;
    for (int i = 0; i < 9; i++) a.p[i] = (const float*)d_in[2 + i];
    a.lc0 = lc0;
    a.pts = pts;
    a.aabb = aabb;
    a.n = npts;

    if (npts <= MAXN) {
        int histBlocks = (npts + 255) / 256;
        prep_kernel<<<16256 + histBlocks, 256>>>(a);
        scan1_kernel<<<32, 1024>>>();
        scatter_kernel<<<(npts + 255) / 256, 256>>>(pts, aabb, npts);
    } else {
        a.n = 0;
        prep_kernel<<<16256, 256>>>(a);
        ident_kernel<<<(npts + 255) / 256, 256>>>(pts, aabb, npts);
    }

    // 4 pts/warp, 8 warps/block -> 32 points/block
    int blocks = (npts + 31) / 32;
    field_kernel<<<blocks, 256>>>(ks, kpb, out, npts);
}

// round 14
// speedup vs baseline: 1.0650x; 1.0650x over previous
#include <cuda_runtime.h>
#include <cuda_fp16.h>

// ---------------------------------------------------------------------------
// KPlaneRBFField on GB300 — round 14.
//  Field = R10 exact (best: 130.5us, 8 pts/warp, 4 lanes/pt).
//  Transpose reworked: 256 pos/block, 8 outstanding float4 loads/thread,
//  __ldcs streaming reads of the fp32 sources. Sort kept (it buys warp-level
//  texel-line sharing at scales 0/1).
// ---------------------------------------------------------------------------

#define NSIDE 64
#define MAXN  524288
#define NBUCK 32768
#define TP_POS 256

__device__ __half   g_planesTh[33030144];  // 66 MB transposed fp16 planes
__device__ __half   g_lc0h[8388608];       // 16.5 MB fp16 codes
__device__ unsigned g_hist[NBUCK];
__device__ unsigned g_blksum[32];
__device__ unsigned g_key[MAXN];
__device__ float4   g_spts[MAXN];          // sorted (xs0,xs1,xs2,pid)

__constant__ int c_plane_off[9] = {
    0,        524288,   1048576,
    1572864,  3670016,  5767168,
    7864320,  16252928, 24641536
};
// blocks/plane @256 pos: {64,64,64,256,256,256,1024,1024,1024}
__constant__ int c_blkCum[10] = {0,64,128,192,448,704,960,1984,3008,4032};
__constant__ int c_res[9]     = {128,128,128,256,256,256,512,512,512};

#define LC0_BLK_END 12224   // 4032 + 8192

struct PrepArgs {
    const float* p[9];
    const float* lc0;
    const float* pts;
    const float* aabb;
    int n;
};

__device__ __forceinline__ unsigned spread3(unsigned x)
{
    x &= 0x3FF;
    x = (x | (x << 16)) & 0x30000FF;
    x = (x | (x << 8))  & 0x300F00F;
    x = (x | (x << 4))  & 0x30C30C3;
    x = (x | (x << 2))  & 0x9249249;
    return x;
}

// ---------------- k1: transpose + lc0 convert + histogram -------------------
__global__ void __launch_bounds__(256) prep_kernel(PrepArgs a)
{
    int b = blockIdx.x;
    int tid = threadIdx.x;

    if (b >= LC0_BLK_END) {                 // Morton histogram
        int i = (b - LC0_BLK_END) * 256 + tid;
        if (i >= a.n) return;
        float a0x = a.aabb[0], a0y = a.aabb[1], a0z = a.aabb[2];
        float a1x = a.aabb[3], a1y = a.aabb[4], a1z = a.aabb[5];
        float x = (a.pts[3 * i + 0] - a0x) * (2.0f / (a1x - a0x)) - 1.0f;
        float y = (a.pts[3 * i + 1] - a0y) * (2.0f / (a1y - a0y)) - 1.0f;
        float z = (a.pts[3 * i + 2] - a0z) * (2.0f / (a1z - a0z)) - 1.0f;
        int qx = min(max((int)((x + 1.0f) * 16.0f), 0), 31);
        int qy = min(max((int)((y + 1.0f) * 16.0f), 0), 31);
        int qz = min(max((int)((z + 1.0f) * 16.0f), 0), 31);
        unsigned key = (spread3(qx) << 2) | (spread3(qy) << 1) | spread3(qz);
        g_key[i] = key;
        atomicAdd(&g_hist[key], 1u);
        return;
    }
    if (b >= 4032) {                        // lc0 convert (8192 blocks)
        int i = (b - 4032) * 256 + tid;
        float4 v = __ldcs((const float4*)a.lc0 + i);
        __half2 h0 = __floats2half2_rn(v.x, v.y);
        __half2 h1 = __floats2half2_rn(v.z, v.w);
        ((uint2*)g_lc0h)[i] = make_uint2(*(unsigned*)&h0, *(unsigned*)&h1);
        return;
    }

    // plane transpose: 256 positions per block
    __shared__ float tile[TP_POS][33];
    int pi = 0;
    #pragma unroll
    for (int i = 1; i < 9; i++) pi += (b >= c_blkCum[i]) ? 1 : 0;
    int r  = c_res[pi];
    int rr = r * r;
    int posBase = (b - c_blkCum[pi]) * TP_POS;
    const float4* src4 = (const float4*)a.p[pi];
    int rr4 = rr >> 2;
    int pb4 = posBase >> 2;

    // 8 independent float4 streaming loads per thread (MLP=8)
    float4 vals[8];
    #pragma unroll
    for (int it = 0; it < 8; it++) {
        int v  = tid + it * 256;            // 0..2047
        int ch = v >> 6;                    // 0..31
        int pv = v & 63;                    // float4 idx within 256 pos
        vals[it] = __ldcs(&src4[ch * rr4 + pb4 + pv]);
    }
    #pragma unroll
    for (int it = 0; it < 8; it++) {
        int v  = tid + it * 256;
        int ch = v >> 6;
        int p  = (v & 63) << 2;
        tile[p + 0][ch] = vals[it].x;
        tile[p + 1][ch] = vals[it].y;
        tile[p + 2][ch] = vals[it].z;
        tile[p + 3][ch] = vals[it].w;
    }
    __syncthreads();

    uint2* dst2 = (uint2*)(g_planesTh + c_plane_off[pi]) + posBase * 8;
    #pragma unroll
    for (int it = 0; it < 8; it++) {
        int v  = tid + it * 256;            // = p*8 + c4idx
        int p  = v >> 3;
        int c4 = (v & 7) << 2;
        __half2 h0 = __floats2half2_rn(tile[p][c4 + 0], tile[p][c4 + 1]);
        __half2 h1 = __floats2half2_rn(tile[p][c4 + 2], tile[p][c4 + 3]);
        dst2[v] = make_uint2(*(unsigned*)&h0, *(unsigned*)&h1);
    }
}

// ---------------- k2: scan ---------------------------------------------------
__global__ void __launch_bounds__(1024) scan1_kernel()
{
    __shared__ unsigned wsum[32];
    int t = threadIdx.x;
    int lane = t & 31;
    int wid = t >> 5;
    int i = blockIdx.x * 1024 + t;
    unsigned v = g_hist[i];

    unsigned x = v;
    #pragma unroll
    for (int off = 1; off < 32; off <<= 1) {
        unsigned y = __shfl_up_sync(0xFFFFFFFFu, x, off);
        if (lane >= off) x += y;
    }
    if (lane == 31) wsum[wid] = x;
    __syncthreads();
    if (wid == 0) {
        unsigned w = wsum[lane];
        unsigned ww = w;
        #pragma unroll
        for (int off = 1; off < 32; off <<= 1) {
            unsigned y = __shfl_up_sync(0xFFFFFFFFu, ww, off);
            if (lane >= off) ww += y;
        }
        wsum[lane] = ww - w;
        if (lane == 31) g_blksum[blockIdx.x] = ww;
    }
    __syncthreads();
    g_hist[i] = x + wsum[wid] - v;
}

// ---------------- k3: scatter -------------------------------------------------
__global__ void scatter_kernel(const float* __restrict__ pts,
                               const float* __restrict__ aabb, int n)
{
    __shared__ unsigned blkoff[32];
    int t = threadIdx.x;
    if (t < 32) {
        unsigned v = g_blksum[t];
        unsigned x = v;
        #pragma unroll
        for (int off = 1; off < 32; off <<= 1) {
            unsigned y = __shfl_up_sync(0xFFFFFFFFu, x, off);
            if (t >= off) x += y;
        }
        blkoff[t] = x - v;
    }
    __syncthreads();

    int i = blockIdx.x * blockDim.x + t;
    if (i >= n) return;
    unsigned key = g_key[i];
    unsigned pos = atomicAdd(&g_hist[key], 1u) + blkoff[key >> 10];

    float a0x = aabb[0], a0y = aabb[1], a0z = aabb[2];
    float a1x = aabb[3], a1y = aabb[4], a1z = aabb[5];
    float xs0 = (pts[3 * i + 0] - a0x) * (2.0f / (a1x - a0x)) - 1.0f;
    float xs1 = (pts[3 * i + 1] - a0y) * (2.0f / (a1y - a0y)) - 1.0f;
    float xs2 = (pts[3 * i + 2] - a0z) * (2.0f / (a1z - a0z)) - 1.0f;
    g_spts[pos] = make_float4(xs0, xs1, xs2, __int_as_float(i));
}

__global__ void ident_kernel(const float* __restrict__ pts,
                             const float* __restrict__ aabb, int n)
{
    int i = blockIdx.x * blockDim.x + threadIdx.x;
    if (i >= n) return;
    float a0x = aabb[0], a0y = aabb[1], a0z = aabb[2];
    float a1x = aabb[3], a1y = aabb[4], a1z = aabb[5];
    float xs0 = (pts[3 * i + 0] - a0x) * (2.0f / (a1x - a0x)) - 1.0f;
    float xs1 = (pts[3 * i + 1] - a0y) * (2.0f / (a1y - a0y)) - 1.0f;
    float xs2 = (pts[3 * i + 2] - a0z) * (2.0f / (a1z - a0z)) - 1.0f;
    g_spts[i] = make_float4(xs0, xs1, xs2, __int_as_float(i));
}

// ---------------- fp16 helpers ----------------------------------------------
__device__ __forceinline__ void h8tof8(uint4 u, float* f)
{
    float2 p;
    p = __half22float2(*(const __half2*)&u.x); f[0] = p.x; f[1] = p.y;
    p = __half22float2(*(const __half2*)&u.y); f[2] = p.x; f[3] = p.y;
    p = __half22float2(*(const __half2*)&u.z); f[4] = p.x; f[5] = p.y;
    p = __half22float2(*(const __half2*)&u.w); f[6] = p.x; f[7] = p.y;
}

// one bilinear sample of 8 channels: 4 LDG.128, x-lerp half2, y-lerp fp32.
__device__ __forceinline__ void sample8(const __half* __restrict__ T, int r,
                                        float u, float v, int c8, float* f)
{
    float fr = (float)(r - 1);
    float fx = (u + 1.0f) * 0.5f * fr;
    float fy = (v + 1.0f) * 0.5f * fr;
    float flx = fminf(fmaxf(floorf(fx), 0.0f), (float)(r - 2));
    float fly = fminf(fmaxf(floorf(fy), 0.0f), (float)(r - 2));
    float wx = fx - flx;
    float wy = fy - fly;
    int ix = (int)flx;
    int iy = (int)fly;
    const uint4* b = (const uint4*)(T + ((iy * r + ix) << 5)) + c8;
    int rs = r << 2;
    uint4 A = __ldg(b);
    uint4 B = __ldg(b + 4);
    uint4 C = __ldg(b + rs);
    uint4 D = __ldg(b + rs + 4);

    __half2 wx2 = __float2half2_rn(wx);
    const __half2* Ah = (const __half2*)&A;
    const __half2* Bh = (const __half2*)&B;
    const __half2* Ch = (const __half2*)&C;
    const __half2* Dh = (const __half2*)&D;
    #pragma unroll
    for (int i = 0; i < 4; i++) {
        __half2 t = __hfma2(__hsub2(Bh[i], Ah[i]), wx2, Ah[i]);
        __half2 o = __hfma2(__hsub2(Dh[i], Ch[i]), wx2, Ch[i]);
        float2 tf = __half22float2(t);
        float2 bf = __half22float2(o);
        f[2 * i + 0] = tf.x + (bf.x - tf.x) * wy;
        f[2 * i + 1] = tf.y + (bf.y - tf.y) * wy;
    }
}

// ---------------- k4: field kernel (R10): 8 pts/warp, 50% occ ----------------
__global__ void __launch_bounds__(256, 4) field_kernel(
    const float* __restrict__ ks,
    const float* __restrict__ kpb,
    float* __restrict__ out,
    int npts)
{
    int gwarp = (int)((blockIdx.x * blockDim.x + threadIdx.x) >> 5);
    int lane  = threadIdx.x & 31;
    int pslot = lane >> 2;
    int c8    = lane & 3;

    int slot = gwarp * 8 + pslot;
    if (slot >= npts) return;

    float4 sp = __ldcs(&g_spts[slot]);
    float xs0 = sp.x, xs1 = sp.y, xs2 = sp.z;
    int pid = __float_as_int(sp.w);

    float* outP = out + (size_t)pid * 128;
    const float4* kpb4 = (const float4*)kpb;

    const int resArr[3] = {128, 256, 512};
    #pragma unroll
    for (int s = 0; s < 3; s++) {
        int r = resArr[s];
        float f0[8], f1[8], f2[8];
        sample8(g_planesTh + c_plane_off[s * 3 + 0], r, xs0, xs1, c8, f0);
        sample8(g_planesTh + c_plane_off[s * 3 + 1], r, xs0, xs2, c8, f1);
        sample8(g_planesTh + c_plane_off[s * 3 + 2], r, xs1, xs2, c8, f2);
        float4 bb0 = __ldg(kpb4 + s * 8 + c8 * 2);
        float4 bb1 = __ldg(kpb4 + s * 8 + c8 * 2 + 1);
        float4 o0, o1;
        o0.x = f0[0] * f1[0] * f2[0] + bb0.x;
        o0.y = f0[1] * f1[1] * f2[1] + bb0.y;
        o0.z = f0[2] * f1[2] * f2[2] + bb0.z;
        o0.w = f0[3] * f1[3] * f2[3] + bb0.w;
        o1.x = f0[4] * f1[4] * f2[4] + bb1.x;
        o1.y = f0[5] * f1[5] * f2[5] + bb1.y;
        o1.z = f0[6] * f1[6] * f2[6] + bb1.z;
        o1.w = f0[7] * f1[7] * f2[7] + bb1.w;
        float* op = outP + s * 32 + (c8 << 3);
        __stcs((float4*)op, o0);
        __stcs((float4*)(op + 4), o1);
    }

    // ---- RBF features over 64^3 grid on [-1,1]
    const float interval = 2.0f / (float)(NSIDE - 1);
    float c0f = fminf(fmaxf(floorf((xs0 + 1.0f) / interval), 0.0f), (float)(NSIDE - 2));
    float c1f = fminf(fmaxf(floorf((xs1 + 1.0f) / interval), 0.0f), (float)(NSIDE - 2));
    float c2f = fminf(fmaxf(floorf((xs2 + 1.0f) / interval), 0.0f), (float)(NSIDE - 2));
    int ci0 = (int)c0f, ci1 = (int)c1f, ci2 = (int)c2f;

    float acc[8] = {0.f, 0.f, 0.f, 0.f, 0.f, 0.f, 0.f, 0.f};
    float wsum = 0.0f;
    #pragma unroll
    for (int g = 0; g < 2; g++) {
        int idxA[4];
        float d2A[4];
        #pragma unroll
        for (int q = 0; q < 4; q++) {
            int k = g * 4 + q;
            int i0 = ci0 + ((k >> 2) & 1);
            int i1 = ci1 + ((k >> 1) & 1);
            int i2 = ci2 + (k & 1);
            idxA[q] = (i0 * NSIDE + i1) * NSIDE + i2;
            float d0 = xs0 - (-1.0f + (float)i0 * interval);
            float d1 = xs1 - (-1.0f + (float)i1 * interval);
            float d2 = xs2 - (-1.0f + (float)i2 * interval);
            d2A[q] = d0 * d0 + d1 * d1 + d2 * d2;
        }
        float svA[4];
        uint4 cuA[4];
        #pragma unroll
        for (int q = 0; q < 4; q++) {
            svA[q] = __ldg(&ks[idxA[q]]);
            cuA[q] = __ldg((const uint4*)(g_lc0h + (idxA[q] << 5)) + c8);
        }
        #pragma unroll
        for (int q = 0; q < 4; q++) {
            float phi = 1.0f / (1.0f + d2A[q] * svA[q] * svA[q]);
            wsum += phi;
            float code[8];
            h8tof8(cuA[q], code);
            #pragma unroll
            for (int j = 0; j < 8; j++) acc[j] += phi * code[j];
        }
    }
    float inv = 1.0f / (wsum + 1e-8f);
    float4 bb0 = __ldg(kpb4 + 24 + c8 * 2);
    float4 bb1 = __ldg(kpb4 + 24 + c8 * 2 + 1);
    float4 o0, o1;
    o0.x = acc[0] * inv + bb0.x;
    o0.y = acc[1] * inv + bb0.y;
    o0.z = acc[2] * inv + bb0.z;
    o0.w = acc[3] * inv + bb0.w;
    o1.x = acc[4] * inv + bb1.x;
    o1.y = acc[5] * inv + bb1.y;
    o1.z = acc[6] * inv + bb1.z;
    o1.w = acc[7] * inv + bb1.w;
    float* op = outP + 96 + (c8 << 3);
    __stcs((float4*)op, o0);
    __stcs((float4*)(op + 4), o1);
}

// ------------------------------ launcher ------------------------------------
extern "C" void kernel_launch(void* const* d_in, const int* in_sizes, int n_in,
                              void* d_out, int out_size)
{
    const float* pts  = (const float*)d_in[0];
    const float* aabb = (const float*)d_in[1];
    const float* lc0  = (const float*)d_in[11];
    const float* ks   = (const float*)d_in[12];
    const float* kpb  = (const float*)d_in[13];
    float* out = (float*)d_out;

    int npts = in_sizes[0] / 3;

    void* histPtr = nullptr;
    cudaGetSymbolAddress(&histPtr, g_hist);
    cudaMemsetAsync(histPtr, 0, NBUCK * sizeof(unsigned));

    PrepArgs a;
    for (int i = 0; i < 9; i++) a.p[i] = (const float*)d_in[2 + i];
    a.lc0 = lc0;
    a.pts = pts;
    a.aabb = aabb;
    a.n = npts;

    if (npts <= MAXN) {
        int histBlocks = (npts + 255) / 256;
        prep_kernel<<<LC0_BLK_END + histBlocks, 256>>>(a);
        scan1_kernel<<<32, 1024>>>();
        scatter_kernel<<<(npts + 255) / 256, 256>>>(pts, aabb, npts);
    } else {
        a.n = 0;
        prep_kernel<<<LC0_BLK_END, 256>>>(a);
        ident_kernel<<<(npts + 255) / 256, 256>>>(pts, aabb, npts);
    }

    int blocks = (npts + 63) / 64;    // 8 pts/warp * 8 warps
    field_kernel<<<blocks, 256>>>(ks, kpb, out, npts);
}

// round 15
// speedup vs baseline: 1.0691x; 1.0039x over previous
#include <cuda_runtime.h>
#include <cuda_fp16.h>

// ---------------------------------------------------------------------------
// KPlaneRBFField on GB300 — round 15.
//  Field = R10/R14 exact (130.3us).
//  Transpose FIXED: previous versions had 8-way smem bank conflicts in the
//  write phase (p-stride 4 over 33-pad rows -> bank stride 4). New mapping:
//  load ch=it / pos=tid (LDG.32 coalesced, lane-stride-1 smem writes ->
//  conflict-free), read phase verified conflict-free. Prep becomes
//  DRAM-bound instead of crossbar-bound.
// ---------------------------------------------------------------------------

#define NSIDE 64
#define MAXN  524288
#define NBUCK 32768
#define TP_POS 256

__device__ __half   g_planesTh[33030144];  // 66 MB transposed fp16 planes
__device__ __half   g_lc0h[8388608];       // 16.5 MB fp16 codes
__device__ unsigned g_hist[NBUCK];
__device__ unsigned g_blksum[32];
__device__ unsigned g_key[MAXN];
__device__ float4   g_spts[MAXN];          // sorted (xs0,xs1,xs2,pid)

__constant__ int c_plane_off[9] = {
    0,        524288,   1048576,
    1572864,  3670016,  5767168,
    7864320,  16252928, 24641536
};
// blocks/plane @256 pos: {64,64,64,256,256,256,1024,1024,1024}
__constant__ int c_blkCum[10] = {0,64,128,192,448,704,960,1984,3008,4032};
__constant__ int c_res[9]     = {128,128,128,256,256,256,512,512,512};

#define LC0_BLK_END 12224   // 4032 + 8192

struct PrepArgs {
    const float* p[9];
    const float* lc0;
    const float* pts;
    const float* aabb;
    int n;
};

__device__ __forceinline__ unsigned spread3(unsigned x)
{
    x &= 0x3FF;
    x = (x | (x << 16)) & 0x30000FF;
    x = (x | (x << 8))  & 0x300F00F;
    x = (x | (x << 4))  & 0x30C30C3;
    x = (x | (x << 2))  & 0x9249249;
    return x;
}

// ---------------- k1: transpose + lc0 convert + histogram -------------------
__global__ void __launch_bounds__(256) prep_kernel(PrepArgs a)
{
    int b = blockIdx.x;
    int tid = threadIdx.x;

    if (b >= LC0_BLK_END) {                 // Morton histogram
        int i = (b - LC0_BLK_END) * 256 + tid;
        if (i >= a.n) return;
        float a0x = a.aabb[0], a0y = a.aabb[1], a0z = a.aabb[2];
        float a1x = a.aabb[3], a1y = a.aabb[4], a1z = a.aabb[5];
        float x = (a.pts[3 * i + 0] - a0x) * (2.0f / (a1x - a0x)) - 1.0f;
        float y = (a.pts[3 * i + 1] - a0y) * (2.0f / (a1y - a0y)) - 1.0f;
        float z = (a.pts[3 * i + 2] - a0z) * (2.0f / (a1z - a0z)) - 1.0f;
        int qx = min(max((int)((x + 1.0f) * 16.0f), 0), 31);
        int qy = min(max((int)((y + 1.0f) * 16.0f), 0), 31);
        int qz = min(max((int)((z + 1.0f) * 16.0f), 0), 31);
        unsigned key = (spread3(qx) << 2) | (spread3(qy) << 1) | spread3(qz);
        g_key[i] = key;
        atomicAdd(&g_hist[key], 1u);
        return;
    }
    if (b >= 4032) {                        // lc0 convert (8192 blocks)
        int i = (b - 4032) * 256 + tid;
        float4 v = __ldcs((const float4*)a.lc0 + i);
        __half2 h0 = __floats2half2_rn(v.x, v.y);
        __half2 h1 = __floats2half2_rn(v.z, v.w);
        ((uint2*)g_lc0h)[i] = make_uint2(*(unsigned*)&h0, *(unsigned*)&h1);
        return;
    }

    // plane transpose: 256 positions per block, conflict-free smem.
    __shared__ float tile[TP_POS][33];
    int pi = 0;
    #pragma unroll
    for (int i = 1; i < 9; i++) pi += (b >= c_blkCum[i]) ? 1 : 0;
    int r  = c_res[pi];
    int rr = r * r;
    int posBase = (b - c_blkCum[pi]) * TP_POS;
    const float* src = a.p[pi];

    // Load: ch = it, pos = posBase + tid. Coalesced LDG.32 (256 floats/instr
    // block-wide), 32 independent loads in flight.
    float va[32];
    #pragma unroll
    for (int it = 0; it < 32; it++)
        va[it] = __ldcs(&src[it * rr + posBase + tid]);
    // Store tile[tid][it]: bank = (33*tid + it) mod 32 = (tid + it) mod 32
    // -> lane stride 1 -> conflict-free.
    #pragma unroll
    for (int it = 0; it < 32; it++)
        tile[tid][it] = va[it];
    __syncthreads();

    // Read tile[p][c4+j] (LDS.32): bank = (p + c4 + j) mod 32; within a warp
    // p spans 4 values (g) and c4 8 values (4h) -> g + 4h distinct -> conflict-free.
    uint2* dst2 = (uint2*)(g_planesTh + c_plane_off[pi]) + posBase * 8;
    #pragma unroll
    for (int it = 0; it < 8; it++) {
        int v  = tid + it * 256;            // = p*8 + c4idx
        int p  = v >> 3;
        int c4 = (v & 7) << 2;
        __half2 h0 = __floats2half2_rn(tile[p][c4 + 0], tile[p][c4 + 1]);
        __half2 h1 = __floats2half2_rn(tile[p][c4 + 2], tile[p][c4 + 3]);
        dst2[v] = make_uint2(*(unsigned*)&h0, *(unsigned*)&h1);
    }
}

// ---------------- k2: scan ---------------------------------------------------
__global__ void __launch_bounds__(1024) scan1_kernel()
{
    __shared__ unsigned wsum[32];
    int t = threadIdx.x;
    int lane = t & 31;
    int wid = t >> 5;
    int i = blockIdx.x * 1024 + t;
    unsigned v = g_hist[i];

    unsigned x = v;
    #pragma unroll
    for (int off = 1; off < 32; off <<= 1) {
        unsigned y = __shfl_up_sync(0xFFFFFFFFu, x, off);
        if (lane >= off) x += y;
    }
    if (lane == 31) wsum[wid] = x;
    __syncthreads();
    if (wid == 0) {
        unsigned w = wsum[lane];
        unsigned ww = w;
        #pragma unroll
        for (int off = 1; off < 32; off <<= 1) {
            unsigned y = __shfl_up_sync(0xFFFFFFFFu, ww, off);
            if (lane >= off) ww += y;
        }
        wsum[lane] = ww - w;
        if (lane == 31) g_blksum[blockIdx.x] = ww;
    }
    __syncthreads();
    g_hist[i] = x + wsum[wid] - v;
}

// ---------------- k3: scatter -------------------------------------------------
__global__ void scatter_kernel(const float* __restrict__ pts,
                               const float* __restrict__ aabb, int n)
{
    __shared__ unsigned blkoff[32];
    int t = threadIdx.x;
    if (t < 32) {
        unsigned v = g_blksum[t];
        unsigned x = v;
        #pragma unroll
        for (int off = 1; off < 32; off <<= 1) {
            unsigned y = __shfl_up_sync(0xFFFFFFFFu, x, off);
            if (t >= off) x += y;
        }
        blkoff[t] = x - v;
    }
    __syncthreads();

    int i = blockIdx.x * blockDim.x + t;
    if (i >= n) return;
    unsigned key = g_key[i];
    unsigned pos = atomicAdd(&g_hist[key], 1u) + blkoff[key >> 10];

    float a0x = aabb[0], a0y = aabb[1], a0z = aabb[2];
    float a1x = aabb[3], a1y = aabb[4], a1z = aabb[5];
    float xs0 = (pts[3 * i + 0] - a0x) * (2.0f / (a1x - a0x)) - 1.0f;
    float xs1 = (pts[3 * i + 1] - a0y) * (2.0f / (a1y - a0y)) - 1.0f;
    float xs2 = (pts[3 * i + 2] - a0z) * (2.0f / (a1z - a0z)) - 1.0f;
    g_spts[pos] = make_float4(xs0, xs1, xs2, __int_as_float(i));
}

__global__ void ident_kernel(const float* __restrict__ pts,
                             const float* __restrict__ aabb, int n)
{
    int i = blockIdx.x * blockDim.x + threadIdx.x;
    if (i >= n) return;
    float a0x = aabb[0], a0y = aabb[1], a0z = aabb[2];
    float a1x = aabb[3], a1y = aabb[4], a1z = aabb[5];
    float xs0 = (pts[3 * i + 0] - a0x) * (2.0f / (a1x - a0x)) - 1.0f;
    float xs1 = (pts[3 * i + 1] - a0y) * (2.0f / (a1y - a0y)) - 1.0f;
    float xs2 = (pts[3 * i + 2] - a0z) * (2.0f / (a1z - a0z)) - 1.0f;
    g_spts[i] = make_float4(xs0, xs1, xs2, __int_as_float(i));
}

// ---------------- fp16 helpers ----------------------------------------------
__device__ __forceinline__ void h8tof8(uint4 u, float* f)
{
    float2 p;
    p = __half22float2(*(const __half2*)&u.x); f[0] = p.x; f[1] = p.y;
    p = __half22float2(*(const __half2*)&u.y); f[2] = p.x; f[3] = p.y;
    p = __half22float2(*(const __half2*)&u.z); f[4] = p.x; f[5] = p.y;
    p = __half22float2(*(const __half2*)&u.w); f[6] = p.x; f[7] = p.y;
}

// one bilinear sample of 8 channels: 4 LDG.128, x-lerp half2, y-lerp fp32.
__device__ __forceinline__ void sample8(const __half* __restrict__ T, int r,
                                        float u, float v, int c8, float* f)
{
    float fr = (float)(r - 1);
    float fx = (u + 1.0f) * 0.5f * fr;
    float fy = (v + 1.0f) * 0.5f * fr;
    float flx = fminf(fmaxf(floorf(fx), 0.0f), (float)(r - 2));
    float fly = fminf(fmaxf(floorf(fy), 0.0f), (float)(r - 2));
    float wx = fx - flx;
    float wy = fy - fly;
    int ix = (int)flx;
    int iy = (int)fly;
    const uint4* b = (const uint4*)(T + ((iy * r + ix) << 5)) + c8;
    int rs = r << 2;
    uint4 A = __ldg(b);
    uint4 B = __ldg(b + 4);
    uint4 C = __ldg(b + rs);
    uint4 D = __ldg(b + rs + 4);

    __half2 wx2 = __float2half2_rn(wx);
    const __half2* Ah = (const __half2*)&A;
    const __half2* Bh = (const __half2*)&B;
    const __half2* Ch = (const __half2*)&C;
    const __half2* Dh = (const __half2*)&D;
    #pragma unroll
    for (int i = 0; i < 4; i++) {
        __half2 t = __hfma2(__hsub2(Bh[i], Ah[i]), wx2, Ah[i]);
        __half2 o = __hfma2(__hsub2(Dh[i], Ch[i]), wx2, Ch[i]);
        float2 tf = __half22float2(t);
        float2 bf = __half22float2(o);
        f[2 * i + 0] = tf.x + (bf.x - tf.x) * wy;
        f[2 * i + 1] = tf.y + (bf.y - tf.y) * wy;
    }
}

// ---------------- k4: field kernel (R10): 8 pts/warp, 50% occ ----------------
__global__ void __launch_bounds__(256, 4) field_kernel(
    const float* __restrict__ ks,
    const float* __restrict__ kpb,
    float* __restrict__ out,
    int npts)
{
    int gwarp = (int)((blockIdx.x * blockDim.x + threadIdx.x) >> 5);
    int lane  = threadIdx.x & 31;
    int pslot = lane >> 2;
    int c8    = lane & 3;

    int slot = gwarp * 8 + pslot;
    if (slot >= npts) return;

    float4 sp = __ldcs(&g_spts[slot]);
    float xs0 = sp.x, xs1 = sp.y, xs2 = sp.z;
    int pid = __float_as_int(sp.w);

    float* outP = out + (size_t)pid * 128;
    const float4* kpb4 = (const float4*)kpb;

    const int resArr[3] = {128, 256, 512};
    #pragma unroll
    for (int s = 0; s < 3; s++) {
        int r = resArr[s];
        float f0[8], f1[8], f2[8];
        sample8(g_planesTh + c_plane_off[s * 3 + 0], r, xs0, xs1, c8, f0);
        sample8(g_planesTh + c_plane_off[s * 3 + 1], r, xs0, xs2, c8, f1);
        sample8(g_planesTh + c_plane_off[s * 3 + 2], r, xs1, xs2, c8, f2);
        float4 bb0 = __ldg(kpb4 + s * 8 + c8 * 2);
        float4 bb1 = __ldg(kpb4 + s * 8 + c8 * 2 + 1);
        float4 o0, o1;
        o0.x = f0[0] * f1[0] * f2[0] + bb0.x;
        o0.y = f0[1] * f1[1] * f2[1] + bb0.y;
        o0.z = f0[2] * f1[2] * f2[2] + bb0.z;
        o0.w = f0[3] * f1[3] * f2[3] + bb0.w;
        o1.x = f0[4] * f1[4] * f2[4] + bb1.x;
        o1.y = f0[5] * f1[5] * f2[5] + bb1.y;
        o1.z = f0[6] * f1[6] * f2[6] + bb1.z;
        o1.w = f0[7] * f1[7] * f2[7] + bb1.w;
        float* op = outP + s * 32 + (c8 << 3);
        __stcs((float4*)op, o0);
        __stcs((float4*)(op + 4), o1);
    }

    // ---- RBF features over 64^3 grid on [-1,1]
    const float interval = 2.0f / (float)(NSIDE - 1);
    float c0f = fminf(fmaxf(floorf((xs0 + 1.0f) / interval), 0.0f), (float)(NSIDE - 2));
    float c1f = fminf(fmaxf(floorf((xs1 + 1.0f) / interval), 0.0f), (float)(NSIDE - 2));
    float c2f = fminf(fmaxf(floorf((xs2 + 1.0f) / interval), 0.0f), (float)(NSIDE - 2));
    int ci0 = (int)c0f, ci1 = (int)c1f, ci2 = (int)c2f;

    float acc[8] = {0.f, 0.f, 0.f, 0.f, 0.f, 0.f, 0.f, 0.f};
    float wsum = 0.0f;
    #pragma unroll
    for (int g = 0; g < 2; g++) {
        int idxA[4];
        float d2A[4];
        #pragma unroll
        for (int q = 0; q < 4; q++) {
            int k = g * 4 + q;
            int i0 = ci0 + ((k >> 2) & 1);
            int i1 = ci1 + ((k >> 1) & 1);
            int i2 = ci2 + (k & 1);
            idxA[q] = (i0 * NSIDE + i1) * NSIDE + i2;
            float d0 = xs0 - (-1.0f + (float)i0 * interval);
            float d1 = xs1 - (-1.0f + (float)i1 * interval);
            float d2 = xs2 - (-1.0f + (float)i2 * interval);
            d2A[q] = d0 * d0 + d1 * d1 + d2 * d2;
        }
        float svA[4];
        uint4 cuA[4];
        #pragma unroll
        for (int q = 0; q < 4; q++) {
            svA[q] = __ldg(&ks[idxA[q]]);
            cuA[q] = __ldg((const uint4*)(g_lc0h + (idxA[q] << 5)) + c8);
        }
        #pragma unroll
        for (int q = 0; q < 4; q++) {
            float phi = 1.0f / (1.0f + d2A[q] * svA[q] * svA[q]);
            wsum += phi;
            float code[8];
            h8tof8(cuA[q], code);
            #pragma unroll
            for (int j = 0; j < 8; j++) acc[j] += phi * code[j];
        }
    }
    float inv = 1.0f / (wsum + 1e-8f);
    float4 bb0 = __ldg(kpb4 + 24 + c8 * 2);
    float4 bb1 = __ldg(kpb4 + 24 + c8 * 2 + 1);
    float4 o0, o1;
    o0.x = acc[0] * inv + bb0.x;
    o0.y = acc[1] * inv + bb0.y;
    o0.z = acc[2] * inv + bb0.z;
    o0.w = acc[3] * inv + bb0.w;
    o1.x = acc[4] * inv + bb1.x;
    o1.y = acc[5] * inv + bb1.y;
    o1.z = acc[6] * inv + bb1.z;
    o1.w = acc[7] * inv + bb1.w;
    float* op = outP + 96 + (c8 << 3);
    __stcs((float4*)op, o0);
    __stcs((float4*)(op + 4), o1);
}

// ------------------------------ launcher ------------------------------------
extern "C" void kernel_launch(void* const* d_in, const int* in_sizes, int n_in,
                              void* d_out, int out_size)
{
    const float* pts  = (const float*)d_in[0];
    const float* aabb = (const float*)d_in[1];
    const float* lc0  = (const float*)d_in[11];
    const float* ks   = (const float*)d_in[12];
    const float* kpb  = (const float*)d_in[13];
    float* out = (float*)d_out;

    int npts = in_sizes[0] / 3;

    void* histPtr = nullptr;
    cudaGetSymbolAddress(&histPtr, g_hist);
    cudaMemsetAsync(histPtr, 0, NBUCK * sizeof(unsigned));

    PrepArgs a;
    for (int i = 0; i < 9; i++) a.p[i] = (const float*)d_in[2 + i];
    a.lc0 = lc0;
    a.pts = pts;
    a.aabb = aabb;
    a.n = npts;

    if (npts <= MAXN) {
        int histBlocks = (npts + 255) / 256;
        prep_kernel<<<LC0_BLK_END + histBlocks, 256>>>(a);
        scan1_kernel<<<32, 1024>>>();
        scatter_kernel<<<(npts + 255) / 256, 256>>>(pts, aabb, npts);
    } else {
        a.n = 0;
        prep_kernel<<<LC0_BLK_END, 256>>>(a);
        ident_kernel<<<(npts + 255) / 256, 256>>>(pts, aabb, npts);
    }

    int blocks = (npts + 63) / 64;    // 8 pts/warp * 8 warps
    field_kernel<<<blocks, 256>>>(ks, kpb, out, npts);
}